// round 2
// baseline (speedup 1.0000x reference)
#include <cuda_runtime.h>

#define NMAX 50000
#define EMAX 1600000
#define HC   64
#define NEG_SLOPE 0.2f

// ---------------- device scratch (no allocation allowed) ----------------
__device__ float g_xl [NMAX * HC];   // source-side transform
__device__ float g_xr [NMAX * HC];   // target-side transform
__device__ float g_h  [NMAX * HC];   // activated layer output
__device__ float g_agg[NMAX * HC];   // unnormalized aggregation
__device__ float g_den[NMAX * 4];    // softmax denominators (per node, per head)
__device__ int   g_is64;             // 1 if edge_index is int64, 0 if int32

__device__ __forceinline__ float lrelu(float v) {
    return v > 0.f ? v : NEG_SLOPE * v;
}

// ---------------- edge_index dtype detection ------------------------------
// int64 node ids < 50000 have zero high words; int32 data has random values
// in the odd word slots. P(false int64 detection) ~ (1/50000)^64 ~ 0.
__global__ void detect_dtype_kernel(const int* __restrict__ w) {
    if (threadIdx.x == 0 && blockIdx.x == 0) {
        int any = 0;
        for (int i = 0; i < 64; i++) any |= w[2 * i + 1];
        g_is64 = (any == 0) ? 1 : 0;
    }
}

// ---------------- GEMM: C[M,NC] = A[M,K] @ W[K,NC] + bias, optional act ----
// BM=128, BN=64, BK=32, 256 threads, 8x4 per-thread tile.
template<int ACT>  // 0 = none, 1 = sigmoid
__global__ void __launch_bounds__(256) gemm_kernel(
    const float* __restrict__ A, const float* __restrict__ W,
    const float* __restrict__ bias, float* __restrict__ C,
    int M, int K, int NC)
{
    __shared__ __align__(16) float As[32][132];   // [k][m], padded
    __shared__ __align__(16) float Ws[32][64];    // [k][n]

    const int tid = threadIdx.x;
    const int bm  = blockIdx.x * 128;
    const int bn  = blockIdx.y * 64;
    const int r0  = (tid >> 4) * 8;   // row offset in tile: 0..120
    const int c0  = (tid & 15) * 4;   // col offset in tile: 0..60

    float acc[8][4];
#pragma unroll
    for (int i = 0; i < 8; i++)
#pragma unroll
        for (int j = 0; j < 4; j++) acc[i][j] = 0.f;

    for (int kk = 0; kk < K; kk += 32) {
        // load A tile (128x32 floats) transposed into As[k][m]
#pragma unroll
        for (int i = 0; i < 4; i++) {
            int f   = tid + i * 256;
            int row = f >> 3;     // 0..127
            int c4  = f & 7;      // 0..7
            float4 v = make_float4(0.f, 0.f, 0.f, 0.f);
            if (bm + row < M)
                v = *(const float4*)(A + (size_t)(bm + row) * K + kk + c4 * 4);
            As[c4 * 4 + 0][row] = v.x;
            As[c4 * 4 + 1][row] = v.y;
            As[c4 * 4 + 2][row] = v.z;
            As[c4 * 4 + 3][row] = v.w;
        }
        // load W tile (32x64 floats)
#pragma unroll
        for (int i = 0; i < 2; i++) {
            int f  = tid + i * 256;
            int kr = f >> 4;          // 0..31
            int cw = (f & 15) * 4;    // 0..60
            *(float4*)&Ws[kr][cw] =
                *(const float4*)(W + (size_t)(kk + kr) * NC + bn + cw);
        }
        __syncthreads();

#pragma unroll
        for (int k = 0; k < 32; k++) {
            float4 a0 = *(const float4*)&As[k][r0];
            float4 a1 = *(const float4*)&As[k][r0 + 4];
            float4 w  = *(const float4*)&Ws[k][c0];
            float av[8] = {a0.x, a0.y, a0.z, a0.w, a1.x, a1.y, a1.z, a1.w};
            float wv[4] = {w.x, w.y, w.z, w.w};
#pragma unroll
            for (int i = 0; i < 8; i++)
#pragma unroll
                for (int j = 0; j < 4; j++)
                    acc[i][j] += av[i] * wv[j];
        }
        __syncthreads();
    }

    float4 bv = *(const float4*)(bias + bn + c0);
    float bvv[4] = {bv.x, bv.y, bv.z, bv.w};
#pragma unroll
    for (int i = 0; i < 8; i++) {
        int row = bm + r0 + i;
        if (row < M) {
            float o[4];
#pragma unroll
            for (int j = 0; j < 4; j++) {
                float v = acc[i][j] + bvv[j];
                if (ACT == 1) v = 1.f / (1.f + __expf(-v));
                o[j] = v;
            }
            *(float4*)(C + (size_t)row * NC + bn + c0) =
                make_float4(o[0], o[1], o[2], o[3]);
        }
    }
}

// ---------------- fused edge kernel -------------------------------------
// 4 threads per edge (one per head). Computes ex = exp(att . lrelu(xl_s + xr_d))
// and accumulates ex into g_den[d,h] and ex*xl_s into g_agg[d,h,:] via reds.
// Softmax normalization is deferred to the finalize kernel (mathematically
// identical to the reference's per-edge alpha; no overflow risk at these
// logit scales).
__global__ void edge_fused_kernel(const void* __restrict__ ei_raw, int E,
                                  const float* __restrict__ att)
{
    __shared__ float satt[64];
    if (threadIdx.x < 64) satt[threadIdx.x] = att[threadIdx.x];
    __syncthreads();

    int gid = blockIdx.x * blockDim.x + threadIdx.x;
    if (gid >= E * 4) return;
    int e = gid >> 2;
    int h = gid & 3;

    int s, d;
    if (g_is64) {
        const long long* p = (const long long*)ei_raw;
        s = (int)p[e];
        d = (int)p[e + E];
    } else {
        const int* p = (const int*)ei_raw;
        s = p[e];
        d = p[e + E];
    }

    const float4* pl = (const float4*)(g_xl + (size_t)s * 64 + h * 16);
    const float4* pr = (const float4*)(g_xr + (size_t)d * 64 + h * 16);

    float4 L[4], R[4];
#pragma unroll
    for (int j = 0; j < 4; j++) { L[j] = pl[j]; R[j] = pr[j]; }

    float acc = 0.f;
#pragma unroll
    for (int j = 0; j < 4; j++) {
        acc += satt[h * 16 + j * 4 + 0] * lrelu(L[j].x + R[j].x);
        acc += satt[h * 16 + j * 4 + 1] * lrelu(L[j].y + R[j].y);
        acc += satt[h * 16 + j * 4 + 2] * lrelu(L[j].z + R[j].z);
        acc += satt[h * 16 + j * 4 + 3] * lrelu(L[j].w + R[j].w);
    }
    float ex = __expf(acc);

    asm volatile("red.global.add.f32 [%0], %1;"
                 :: "l"(g_den + (size_t)d * 4 + h), "f"(ex) : "memory");

    float* dp = g_agg + (size_t)d * 64 + h * 16;
#pragma unroll
    for (int j = 0; j < 4; j++) {
        asm volatile("red.global.add.v4.f32 [%0], {%1,%2,%3,%4};"
                     :: "l"(dp + j * 4),
                        "f"(ex * L[j].x), "f"(ex * L[j].y),
                        "f"(ex * L[j].z), "f"(ex * L[j].w)
                     : "memory");
    }
}

// ---------------- finalize: divide by denom, add bias, relu --------------
__global__ void finalize_relu_kernel(const float* __restrict__ bias,
                                     float* __restrict__ out, int n)
{
    int i = blockIdx.x * blockDim.x + threadIdx.x;
    if (i >= n) return;
    int node = i >> 6;
    int hh   = (i >> 4) & 3;
    float den = g_den[node * 4 + hh];
    float v = (den > 0.f) ? (g_agg[i] / den) : 0.f;
    v += bias[i & 63];
    out[i] = fmaxf(v, 0.f);
}

// ---------------- launch --------------------------------------------------
extern "C" void kernel_launch(void* const* d_in, const int* in_sizes, int n_in,
                              void* d_out, int out_size)
{
    const float* x    = (const float*)d_in[0];
    const void*  ei   = d_in[1];
    const float* Wl1  = (const float*)d_in[2];
    const float* bl1  = (const float*)d_in[3];
    const float* Wr1  = (const float*)d_in[4];
    const float* br1  = (const float*)d_in[5];
    const float* att1 = (const float*)d_in[6];
    const float* bias1= (const float*)d_in[7];
    const float* Wl2  = (const float*)d_in[8];
    const float* bl2  = (const float*)d_in[9];
    const float* Wr2  = (const float*)d_in[10];
    const float* br2  = (const float*)d_in[11];
    const float* att2 = (const float*)d_in[12];
    const float* bias2= (const float*)d_in[13];
    const float* Wo   = (const float*)d_in[14];
    const float* bo   = (const float*)d_in[15];

    const int Nn = in_sizes[0] / 256;      // 50000
    const int E  = in_sizes[1] / 2;        // 1600000

    float *p_xl, *p_xr, *p_h, *p_agg, *p_den;
    cudaGetSymbolAddress((void**)&p_xl,  g_xl);
    cudaGetSymbolAddress((void**)&p_xr,  g_xr);
    cudaGetSymbolAddress((void**)&p_h,   g_h);
    cudaGetSymbolAddress((void**)&p_agg, g_agg);
    cudaGetSymbolAddress((void**)&p_den, g_den);

    const int gm = (Nn + 127) / 128;
    const dim3 blk(256);
    const int eb = (E * 4 + 255) / 256;
    const int fb = (Nn * 64 + 255) / 256;

    detect_dtype_kernel<<<1, 32>>>((const int*)ei);

    // ---- layer 1 ----
    gemm_kernel<0><<<dim3(gm, 1), blk>>>(x, Wl1, bl1, p_xl, Nn, 256, 64);
    gemm_kernel<0><<<dim3(gm, 1), blk>>>(x, Wr1, br1, p_xr, Nn, 256, 64);
    cudaMemsetAsync(p_den, 0, (size_t)Nn * 4  * sizeof(float));
    cudaMemsetAsync(p_agg, 0, (size_t)Nn * 64 * sizeof(float));
    edge_fused_kernel<<<eb, blk>>>(ei, E, att1);
    finalize_relu_kernel<<<fb, blk>>>(bias1, p_h, Nn * 64);

    // ---- layer 2 ----
    gemm_kernel<0><<<dim3(gm, 1), blk>>>(p_h, Wl2, bl2, p_xl, Nn, 64, 64);
    gemm_kernel<0><<<dim3(gm, 1), blk>>>(p_h, Wr2, br2, p_xr, Nn, 64, 64);
    cudaMemsetAsync(p_den, 0, (size_t)Nn * 4  * sizeof(float));
    cudaMemsetAsync(p_agg, 0, (size_t)Nn * 64 * sizeof(float));
    edge_fused_kernel<<<eb, blk>>>(ei, E, att2);
    finalize_relu_kernel<<<fb, blk>>>(bias2, p_h, Nn * 64);

    // ---- output head: sigmoid(h @ Wo + bo) -> d_out ----
    gemm_kernel<1><<<dim3(gm, 4), blk>>>(p_h, Wo, bo, (float*)d_out, Nn, 64, 256);
}

// round 3
// speedup vs baseline: 1.3566x; 1.3566x over previous
#include <cuda_runtime.h>

#define NMAX 50000
#define EMAX 1600000
#define HC   64
#define NEG_SLOPE 0.2f

// ---------------- device scratch (no allocation allowed) ----------------
__device__ float g_xl [NMAX * HC];     // source-side transform
__device__ float g_xr [NMAX * HC];     // target-side transform
__device__ float g_h  [NMAX * HC];     // activated layer output
__device__ int   g_deg[NMAX];          // in-degree histogram
__device__ int   g_off[NMAX + 1];      // CSR offsets
__device__ int   g_pos[NMAX];          // scatter cursors
__device__ int   g_csr_src[EMAX];      // src node per CSR slot (sorted by dst)
__device__ int   g_is64;               // 1 if edge_index is int64, 0 if int32

__device__ __forceinline__ float lrelu(float v) {
    return v > 0.f ? v : NEG_SLOPE * v;
}

// ---------------- edge_index dtype detection ------------------------------
// int64 node ids < 50000 have zero high words; int32 data has random values
// in the odd word slots. P(false int64 detection) ~ (1/50000)^64 ~ 0.
__global__ void detect_dtype_kernel(const int* __restrict__ w) {
    if (threadIdx.x == 0 && blockIdx.x == 0) {
        int any = 0;
        for (int i = 0; i < 64; i++) any |= w[2 * i + 1];
        g_is64 = (any == 0) ? 1 : 0;
    }
}

__device__ __forceinline__ int load_idx(const void* ei, int i) {
    return g_is64 ? (int)((const long long*)ei)[i] : ((const int*)ei)[i];
}

// ---------------- CSR build ----------------------------------------------
__global__ void hist_kernel(const void* __restrict__ ei, int E) {
    int e = blockIdx.x * blockDim.x + threadIdx.x;
    if (e >= E) return;
    atomicAdd(&g_deg[load_idx(ei, e + E)], 1);
}

// single block, 1024 threads: exclusive scan of g_deg -> g_off, g_pos
__global__ void __launch_bounds__(1024) scan_kernel(int N) {
    __shared__ int part[1024];
    int t = threadIdx.x;
    int chunk = (N + 1023) >> 10;
    int b = t * chunk; if (b > N) b = N;
    int e = b + chunk; if (e > N) e = N;
    int s = 0;
    for (int i = b; i < e; i++) s += g_deg[i];
    part[t] = s;
    __syncthreads();
    for (int d = 1; d < 1024; d <<= 1) {
        int v = (t >= d) ? part[t - d] : 0;
        __syncthreads();
        part[t] += v;
        __syncthreads();
    }
    int run = (t == 0) ? 0 : part[t - 1];
    for (int i = b; i < e; i++) {
        g_off[i] = run;
        g_pos[i] = run;
        run += g_deg[i];
    }
    if (e == N) g_off[N] = run;   // all threads past the end write the total
}

__global__ void scatter_kernel(const void* __restrict__ ei, int E) {
    int e = blockIdx.x * blockDim.x + threadIdx.x;
    if (e >= E) return;
    int s = load_idx(ei, e);
    int d = load_idx(ei, e + E);
    int slot = atomicAdd(&g_pos[d], 1);
    g_csr_src[slot] = s;
}

// ---------------- GEMM: C[M,NC] = A[M,K] @ W[K,NC] + bias, optional act ----
// BM=128, BN=64, BK=32, 256 threads, 8x4 per-thread tile.
template<int ACT>  // 0 = none, 1 = sigmoid
__global__ void __launch_bounds__(256) gemm_kernel(
    const float* __restrict__ A, const float* __restrict__ W,
    const float* __restrict__ bias, float* __restrict__ C,
    int M, int K, int NC)
{
    __shared__ __align__(16) float As[32][132];   // [k][m], padded
    __shared__ __align__(16) float Ws[32][64];    // [k][n]

    const int tid = threadIdx.x;
    const int bm  = blockIdx.x * 128;
    const int bn  = blockIdx.y * 64;
    const int r0  = (tid >> 4) * 8;
    const int c0  = (tid & 15) * 4;

    float acc[8][4];
#pragma unroll
    for (int i = 0; i < 8; i++)
#pragma unroll
        for (int j = 0; j < 4; j++) acc[i][j] = 0.f;

    for (int kk = 0; kk < K; kk += 32) {
#pragma unroll
        for (int i = 0; i < 4; i++) {
            int f   = tid + i * 256;
            int row = f >> 3;
            int c4  = f & 7;
            float4 v = make_float4(0.f, 0.f, 0.f, 0.f);
            if (bm + row < M)
                v = *(const float4*)(A + (size_t)(bm + row) * K + kk + c4 * 4);
            As[c4 * 4 + 0][row] = v.x;
            As[c4 * 4 + 1][row] = v.y;
            As[c4 * 4 + 2][row] = v.z;
            As[c4 * 4 + 3][row] = v.w;
        }
#pragma unroll
        for (int i = 0; i < 2; i++) {
            int f  = tid + i * 256;
            int kr = f >> 4;
            int cw = (f & 15) * 4;
            *(float4*)&Ws[kr][cw] =
                *(const float4*)(W + (size_t)(kk + kr) * NC + bn + cw);
        }
        __syncthreads();

#pragma unroll
        for (int k = 0; k < 32; k++) {
            float4 a0 = *(const float4*)&As[k][r0];
            float4 a1 = *(const float4*)&As[k][r0 + 4];
            float4 w  = *(const float4*)&Ws[k][c0];
            float av[8] = {a0.x, a0.y, a0.z, a0.w, a1.x, a1.y, a1.z, a1.w};
            float wv[4] = {w.x, w.y, w.z, w.w};
#pragma unroll
            for (int i = 0; i < 8; i++)
#pragma unroll
                for (int j = 0; j < 4; j++)
                    acc[i][j] += av[i] * wv[j];
        }
        __syncthreads();
    }

    float4 bv = *(const float4*)(bias + bn + c0);
    float bvv[4] = {bv.x, bv.y, bv.z, bv.w};
#pragma unroll
    for (int i = 0; i < 8; i++) {
        int row = bm + r0 + i;
        if (row < M) {
            float o[4];
#pragma unroll
            for (int j = 0; j < 4; j++) {
                float v = acc[i][j] + bvv[j];
                if (ACT == 1) v = 1.f / (1.f + __expf(-v));
                o[j] = v;
            }
            *(float4*)(C + (size_t)row * NC + bn + c0) =
                make_float4(o[0], o[1], o[2], o[3]);
        }
    }
}

// ---------------- fused per-node GATv2 aggregation ------------------------
// One warp per destination node. Lane c owns channels {2c, 2c+1}.
// For every incoming edge: gather xl[src], logit via 8-lane butterfly reduce
// per head, exp, accumulate numerator/denominator in registers.
// Softmax normalization + bias + relu fused into the epilogue.
__device__ __forceinline__ void gat_edge_step(
    float2 xv, float2 xrv, float a0, float a1,
    float& accx, float& accy, float& den)
{
    float p = a0 * lrelu(xv.x + xrv.x) + a1 * lrelu(xv.y + xrv.y);
    p += __shfl_xor_sync(0xffffffffu, p, 1);
    p += __shfl_xor_sync(0xffffffffu, p, 2);
    p += __shfl_xor_sync(0xffffffffu, p, 4);
    float ex = __expf(p);
    den  += ex;
    accx += ex * xv.x;
    accy += ex * xv.y;
}

__global__ void __launch_bounds__(256) gat_aggregate_kernel(
    const float* __restrict__ xl, const float* __restrict__ xr,
    const float* __restrict__ att, const float* __restrict__ bias,
    float* __restrict__ out, int N)
{
    int warp = (blockIdx.x * blockDim.x + threadIdx.x) >> 5;
    int c    = threadIdx.x & 31;
    if (warp >= N) return;
    const int d = warp;

    const float a0 = att[2 * c];
    const float a1 = att[2 * c + 1];
    const float2 xrv = *(const float2*)(xr + (size_t)d * 64 + 2 * c);

    const int beg = g_off[d];
    const int end = g_off[d + 1];

    float accx = 0.f, accy = 0.f, den = 0.f;

    for (int i = beg; i < end; ) {
        int cnt = end - i;
        if (cnt > 32) cnt = 32;
        int my_src = (c < cnt) ? g_csr_src[i + c] : 0;

        int j = 0;
        for (; j + 4 <= cnt; j += 4) {
            int s0 = __shfl_sync(0xffffffffu, my_src, j);
            int s1 = __shfl_sync(0xffffffffu, my_src, j + 1);
            int s2 = __shfl_sync(0xffffffffu, my_src, j + 2);
            int s3 = __shfl_sync(0xffffffffu, my_src, j + 3);
            float2 v0 = *(const float2*)(xl + (size_t)s0 * 64 + 2 * c);
            float2 v1 = *(const float2*)(xl + (size_t)s1 * 64 + 2 * c);
            float2 v2 = *(const float2*)(xl + (size_t)s2 * 64 + 2 * c);
            float2 v3 = *(const float2*)(xl + (size_t)s3 * 64 + 2 * c);
            gat_edge_step(v0, xrv, a0, a1, accx, accy, den);
            gat_edge_step(v1, xrv, a0, a1, accx, accy, den);
            gat_edge_step(v2, xrv, a0, a1, accx, accy, den);
            gat_edge_step(v3, xrv, a0, a1, accx, accy, den);
        }
        for (; j < cnt; j++) {
            int s = __shfl_sync(0xffffffffu, my_src, j);
            float2 v = *(const float2*)(xl + (size_t)s * 64 + 2 * c);
            gat_edge_step(v, xrv, a0, a1, accx, accy, den);
        }
        i += cnt;
    }

    float inv = (den > 0.f) ? (1.f / den) : 0.f;
    float ox = fmaxf(accx * inv + bias[2 * c],     0.f);
    float oy = fmaxf(accy * inv + bias[2 * c + 1], 0.f);
    *(float2*)(out + (size_t)d * 64 + 2 * c) = make_float2(ox, oy);
}

// ---------------- launch --------------------------------------------------
extern "C" void kernel_launch(void* const* d_in, const int* in_sizes, int n_in,
                              void* d_out, int out_size)
{
    const float* x    = (const float*)d_in[0];
    const void*  ei   = d_in[1];
    const float* Wl1  = (const float*)d_in[2];
    const float* bl1  = (const float*)d_in[3];
    const float* Wr1  = (const float*)d_in[4];
    const float* br1  = (const float*)d_in[5];
    const float* att1 = (const float*)d_in[6];
    const float* bias1= (const float*)d_in[7];
    const float* Wl2  = (const float*)d_in[8];
    const float* bl2  = (const float*)d_in[9];
    const float* Wr2  = (const float*)d_in[10];
    const float* br2  = (const float*)d_in[11];
    const float* att2 = (const float*)d_in[12];
    const float* bias2= (const float*)d_in[13];
    const float* Wo   = (const float*)d_in[14];
    const float* bo   = (const float*)d_in[15];

    const int Nn = in_sizes[0] / 256;      // 50000
    const int E  = in_sizes[1] / 2;        // 1600000

    float *p_xl, *p_xr, *p_h;
    int *p_deg;
    cudaGetSymbolAddress((void**)&p_xl,  g_xl);
    cudaGetSymbolAddress((void**)&p_xr,  g_xr);
    cudaGetSymbolAddress((void**)&p_h,   g_h);
    cudaGetSymbolAddress((void**)&p_deg, g_deg);

    const int gm = (Nn + 127) / 128;
    const dim3 blk(256);
    const int ebl = (E + 255) / 256;
    const int agb = (Nn * 32 + 255) / 256;

    // ---- CSR build (shared by both layers) ----
    detect_dtype_kernel<<<1, 32>>>((const int*)ei);
    cudaMemsetAsync(p_deg, 0, (size_t)Nn * sizeof(int));
    hist_kernel<<<ebl, blk>>>(ei, E);
    scan_kernel<<<1, 1024>>>(Nn);
    scatter_kernel<<<ebl, blk>>>(ei, E);

    // ---- layer 1 ----
    gemm_kernel<0><<<dim3(gm, 1), blk>>>(x, Wl1, bl1, p_xl, Nn, 256, 64);
    gemm_kernel<0><<<dim3(gm, 1), blk>>>(x, Wr1, br1, p_xr, Nn, 256, 64);
    gat_aggregate_kernel<<<agb, blk>>>(p_xl, p_xr, att1, bias1, p_h, Nn);

    // ---- layer 2 ----
    gemm_kernel<0><<<dim3(gm, 1), blk>>>(p_h, Wl2, bl2, p_xl, Nn, 64, 64);
    gemm_kernel<0><<<dim3(gm, 1), blk>>>(p_h, Wr2, br2, p_xr, Nn, 64, 64);
    gat_aggregate_kernel<<<agb, blk>>>(p_xl, p_xr, att2, bias2, p_h, Nn);

    // ---- output head: sigmoid(h @ Wo + bo) -> d_out ----
    gemm_kernel<1><<<dim3(gm, 4), blk>>>(p_h, Wo, bo, (float*)d_out, Nn, 64, 256);
}